// round 8
// baseline (speedup 1.0000x reference)
#include <cuda_runtime.h>
#include <cstdint>

#define D_MODEL      4096
#define NUM_EXPERTS  64
#define N_TOKENS     16384
#define M_TILE       128
#define BK           32
#define N_CHUNKS     (D_MODEL / BK)          // 128
#define THREADS      256
#define STAGES       4
#define A_BYTES      (M_TILE * BK * 4)       // 16384
#define B_BYTES      (BK * NUM_EXPERTS * 4)  // 8192
#define STAGE_BYTES  (A_BYTES + B_BYTES)     // 24576
#define SMEM_DYN     (STAGES * STAGE_BYTES)  // 98304
#define L_STRIDE     68                      // logits tile: 128*68*4 = 34816 B
#define AMB_OFF      36864                   // amb list region (after Ls)
#define EPS_AMB      1e-3f                   // >> measured ~2e-5 MMA noise

// ---------------------------------------------------------------------------
// helpers
// ---------------------------------------------------------------------------
__device__ __forceinline__ uint32_t smem_u32(const void* p) {
    uint32_t a;
    asm("{ .reg .u64 t; cvta.to.shared.u64 t, %1; cvt.u32.u64 %0, t; }"
        : "=r"(a) : "l"(p));
    return a;
}

__device__ __forceinline__ void cp16(uint32_t dst, const float* src) {
    asm volatile("cp.async.cg.shared.global [%0], [%1], 16;"
                 :: "r"(dst), "l"(src) : "memory");
}
#define CP_COMMIT()  asm volatile("cp.async.commit_group;" ::: "memory")
#define CP_WAIT(n)   asm volatile("cp.async.wait_group %0;" :: "n"(n) : "memory")

// m16n8k8 tf32 mma, fp32 accumulate (base ISA -> HMMA on sm_103)
__device__ __forceinline__ void mma_tf32(float* c, const uint32_t* a,
                                         const uint32_t* b) {
    asm volatile(
        "mma.sync.aligned.m16n8k8.row.col.f32.tf32.tf32.f32 "
        "{%0,%1,%2,%3}, {%4,%5,%6,%7}, {%8,%9}, {%0,%1,%2,%3};"
        : "+f"(c[0]), "+f"(c[1]), "+f"(c[2]), "+f"(c[3])
        : "r"(a[0]), "r"(a[1]), "r"(a[2]), "r"(a[3]), "r"(b[0]), "r"(b[1]));
}

// mask split: hi = valid tf32 (alu pipe), lo = x - hi (exact)
__device__ __forceinline__ void split2(float x, uint32_t& hi, uint32_t& lo) {
    uint32_t h = __float_as_uint(x) & 0xFFFFE000u;
    hi = h;
    lo = __float_as_uint(__fsub_rn(x, __uint_as_float(h)));
}

struct AmbEntry {               // 72 B, 128 entries max = 9216 B
    int   token;
    int   nS;
    int   idx[8];
    float pr[8];
};

// ---------------------------------------------------------------------------
// fused router kernel: 3xTF32 mma.sync GEMM + softmax + top-2 + exact recheck
// ---------------------------------------------------------------------------
__global__ __launch_bounds__(THREADS, 1)
void router_mma_kernel(const float* __restrict__ x,
                       const float* __restrict__ W,
                       const float* __restrict__ bias,
                       float* __restrict__ probs,
                       float* __restrict__ topk_p,
                       float* __restrict__ topk_i)
{
    extern __shared__ char smem[];
    __shared__ float bias_s[NUM_EXPERTS];
    __shared__ int n_amb;

    const int tid  = threadIdx.x;
    const int wid  = tid >> 5;
    const int lane = tid & 31;
    const int m0   = blockIdx.x * M_TILE;

    if (tid < NUM_EXPERTS) bias_s[tid] = bias[tid];

    const uint32_t smem_base = smem_u32(smem);

    // ---- async tile loader (chunk it -> stage s), xor-swizzled smem ----
    auto load_chunk = [&](int it, int s) {
        const uint32_t Ab = smem_base + s * STAGE_BYTES;
        const uint32_t Bb = Ab + A_BYTES;
        const float* xg = x + (size_t)m0 * D_MODEL + it * BK;
#pragma unroll
        for (int i = 0; i < 4; i++) {
            int ci  = tid + 256 * i;              // 1024 x 16B
            int row = ci >> 3, q = ci & 7;
            uint32_t w = row * 32 + ((q * 4) ^ ((row & 7) * 4));
            cp16(Ab + w * 4, xg + (size_t)row * D_MODEL + q * 4);
        }
        const float* wg = W + (size_t)it * BK * NUM_EXPERTS;
#pragma unroll
        for (int i = 0; i < 2; i++) {
            int ci = tid + 256 * i;               // 512 x 16B
            int k = ci >> 4, q = ci & 15;
            uint32_t w = k * 64 + ((q * 4) ^ ((k & 7) * 4));
            cp16(Bb + w * 4, wg + k * 64 + q * 4);
        }
    };

#pragma unroll
    for (int s = 0; s < STAGES - 1; s++) { load_chunk(s, s); CP_COMMIT(); }

    // warp tiling: 4x2 warps of 32x32
    const int wr = wid >> 1;
    const int wc = wid & 1;
    const int g  = lane >> 2;
    const int t  = lane & 3;

    float acc[2][4][4];
#pragma unroll
    for (int mf = 0; mf < 2; mf++)
#pragma unroll
        for (int nf = 0; nf < 4; nf++)
#pragma unroll
            for (int j = 0; j < 4; j++) acc[mf][nf][j] = 0.0f;

    const int sw4g = g * 4;

    for (int it = 0; it < N_CHUNKS; ++it) {
        CP_WAIT(STAGES - 2);
        __syncthreads();
        if (it + STAGES - 1 < N_CHUNKS)
            load_chunk(it + STAGES - 1, (it + STAGES - 1) % STAGES);
        CP_COMMIT();

        const float* As = (const float*)(smem + (it % STAGES) * STAGE_BYTES);
        const float* Bs = As + M_TILE * BK;

#pragma unroll
        for (int ks = 0; ks < 4; ks++) {
            const int kb = ks * 8;

            uint32_t ahi[2][4], alo[2][4];
            const int c0s = (kb + t) ^ sw4g;
            const int c1s = (kb + t + 4) ^ sw4g;
#pragma unroll
            for (int mf = 0; mf < 2; mf++) {
                const int r0 = wr * 32 + mf * 16 + g;
                float a0 = As[(r0    ) * 32 + c0s];
                float a1 = As[(r0 + 8) * 32 + c0s];
                float a2 = As[(r0    ) * 32 + c1s];
                float a3 = As[(r0 + 8) * 32 + c1s];
                split2(a0, ahi[mf][0], alo[mf][0]);
                split2(a1, ahi[mf][1], alo[mf][1]);
                split2(a2, ahi[mf][2], alo[mf][2]);
                split2(a3, ahi[mf][3], alo[mf][3]);
            }

            uint32_t bhi[4][2], blo[4][2];
#pragma unroll
            for (int nf = 0; nf < 4; nf++) {
                const int col = wc * 32 + nf * 8 + g;
                float b0 = Bs[(kb + t    ) * 64 + (col ^ (4 * t))];
                float b1 = Bs[(kb + t + 4) * 64 + (col ^ (4 * t + 16))];
                split2(b0, bhi[nf][0], blo[nf][0]);
                split2(b1, bhi[nf][1], blo[nf][1]);
            }

#pragma unroll
            for (int mf = 0; mf < 2; mf++)
#pragma unroll
                for (int nf = 0; nf < 4; nf++) {
                    mma_tf32(acc[mf][nf], ahi[mf], bhi[nf]);
                    mma_tf32(acc[mf][nf], ahi[mf], blo[nf]);
                    mma_tf32(acc[mf][nf], alo[mf], bhi[nf]);
                }
        }
        __syncthreads();
    }

    // ---- fragments -> smem logits tile ----
    float* Ls = (float*)smem;
#pragma unroll
    for (int mf = 0; mf < 2; mf++) {
        const int r = wr * 32 + mf * 16 + g;
#pragma unroll
        for (int nf = 0; nf < 4; nf++) {
            const int c = wc * 32 + nf * 8 + t * 2;
            Ls[ r      * L_STRIDE + c    ] = acc[mf][nf][0];
            Ls[ r      * L_STRIDE + c + 1] = acc[mf][nf][1];
            Ls[(r + 8) * L_STRIDE + c    ] = acc[mf][nf][2];
            Ls[(r + 8) * L_STRIDE + c + 1] = acc[mf][nf][3];
        }
    }
    if (tid == 0) n_amb = 0;
    __syncthreads();

    AmbEntry* amb = (AmbEntry*)(smem + AMB_OFF);

    // ---- one thread per token: bias + softmax + top-2 (+ ambiguity test) ----
    if (tid < M_TILE) {
        const float* lrow = Ls + (size_t)tid * L_STRIDE;
        float d[NUM_EXPERTS];
#pragma unroll
        for (int j = 0; j < NUM_EXPERTS; j++) d[j] = lrow[j] + bias_s[j];

        float mx = -1e30f;
#pragma unroll
        for (int j = 0; j < NUM_EXPERTS; j++) mx = fmaxf(mx, d[j]);
        float ssum = 0.0f;
#pragma unroll
        for (int j = 0; j < NUM_EXPERTS; j++) { d[j] = __expf(d[j] - mx); ssum += d[j]; }
        float inv = 1.0f / ssum;

        float v0 = -1.0f, v1 = -1.0f, v2 = -1.0f;
        int   i0 = 0,     i1 = 0;
#pragma unroll
        for (int j = 0; j < NUM_EXPERTS; j++) {
            float p = d[j] * inv; d[j] = p;
            if (p > v0)      { v2 = v1; v1 = v0; i1 = i0; v0 = p; i0 = j; }
            else if (p > v1) { v2 = v1; v1 = p;  i1 = j; }
            else if (p > v2) { v2 = p; }
        }

        const int token = m0 + tid;
        float* row = probs + (size_t)token * NUM_EXPERTS;
#pragma unroll
        for (int j = 0; j < NUM_EXPERTS / 4; j++)
            *(float4*)(row + 4 * j) =
                make_float4(d[4*j], d[4*j+1], d[4*j+2], d[4*j+3]);

        const bool ambiguous = (v0 - v1 < EPS_AMB) || (v1 - v2 < EPS_AMB);
        if (!ambiguous) {
            float denom = 1.0f / (v0 + v1 + 1e-9f);
            topk_p[(size_t)token * 2 + 0] = v0 * denom;
            topk_p[(size_t)token * 2 + 1] = v1 * denom;
            topk_i[(size_t)token * 2 + 0] = (float)i0;
            topk_i[(size_t)token * 2 + 1] = (float)i1;
        } else {
            int slot = atomicAdd(&n_amb, 1);
            AmbEntry& E = amb[slot];
            E.token = token;
            // candidate set: i0, i1 first, then everything within EPS of v1
            E.idx[0] = i0; E.pr[0] = v0;
            E.idx[1] = i1; E.pr[1] = v1;
            int nS = 2;
            const float thresh = v1 - EPS_AMB;
#pragma unroll
            for (int j = 0; j < NUM_EXPERTS; j++) {
                if (j != i0 && j != i1 && d[j] >= thresh && nS < 8) {
                    E.idx[nS] = j; E.pr[nS] = d[j]; nS++;
                }
            }
            E.nS = nS;
        }
    }
    __syncthreads();

    // ---- warp-cooperative exact recheck of ambiguous tokens ----
    const int na = n_amb;
    for (int e = wid; e < na; e += 8) {
        AmbEntry& E = amb[e];
        const int nS = E.nS;
        int js[8];
#pragma unroll
        for (int s = 0; s < 8; s++) js[s] = (s < nS) ? E.idx[s] : 0;

        float av[8];
#pragma unroll
        for (int s = 0; s < 8; s++) av[s] = 0.0f;

        const float* xr = x + (size_t)E.token * D_MODEL;
        for (int k = lane; k < D_MODEL; k += 32) {
            float xv = xr[k];
            const float* wrow = W + (size_t)k * NUM_EXPERTS;
#pragma unroll
            for (int s = 0; s < 8; s++)
                if (s < nS) av[s] = fmaf(xv, wrow[js[s]], av[s]);
        }
#pragma unroll
        for (int off = 16; off > 0; off >>= 1)
#pragma unroll
            for (int s = 0; s < 8; s++)
                av[s] += __shfl_xor_sync(0xFFFFFFFFu, av[s], off);

        if (lane == 0) {
            float bl = -1e30f, sl = -1e30f;   // best/second exact logits
            int   bj = 1 << 30, sj = 1 << 30;
            float bp = 0.0f,   sp = 0.0f;     // their noisy probs
            for (int s = 0; s < nS; s++) {
                float lg = av[s] + bias_s[js[s]];
                int   j  = js[s];
                float p  = E.pr[s];
                if (lg > bl || (lg == bl && j < bj)) {
                    sl = bl; sj = bj; sp = bp;
                    bl = lg; bj = j;  bp = p;
                } else if (lg > sl || (lg == sl && j < sj)) {
                    sl = lg; sj = j; sp = p;
                }
            }
            float denom = 1.0f / (bp + sp + 1e-9f);
            topk_p[(size_t)E.token * 2 + 0] = bp * denom;
            topk_p[(size_t)E.token * 2 + 1] = sp * denom;
            topk_i[(size_t)E.token * 2 + 0] = (float)bj;
            topk_i[(size_t)E.token * 2 + 1] = (float)sj;
        }
    }
}

// ---------------------------------------------------------------------------
extern "C" void kernel_launch(void* const* d_in, const int* in_sizes, int n_in,
                              void* d_out, int out_size)
{
    const float* x = (const float*)d_in[0];
    const float* W = (const float*)d_in[1];
    const float* b = (const float*)d_in[2];

    float* out    = (float*)d_out;
    float* probs  = out;                                    // 16384*64
    float* topk_p = out + (size_t)N_TOKENS * NUM_EXPERTS;   // 16384*2
    float* topk_i = topk_p + (size_t)N_TOKENS * 2;          // 16384*2

    cudaFuncSetAttribute(router_mma_kernel,
                         cudaFuncAttributeMaxDynamicSharedMemorySize, SMEM_DYN);
    router_mma_kernel<<<N_TOKENS / M_TILE, THREADS, SMEM_DYN>>>(
        x, W, b, probs, topk_p, topk_i);
}